// round 15
// baseline (speedup 1.0000x reference)
#include <cuda_runtime.h>
#include <cuda_bf16.h>
#include <cstdint>

#define DM   1024
#define NH   16
#define HD   64
#define BATCH 2
#define SEQ  2048
#define MTOK (BATCH*SEQ)   // 4096

// ---------------------------------------------------------------------------
// Scratch (allocation-free rule: __device__ globals)
// ---------------------------------------------------------------------------
static __device__ __nv_bfloat16 g_ah[3*MTOK*DM]; // act hi: z=0 Q / attn-out, z=1 K, z=2 V
static __device__ __nv_bfloat16 g_al[3*MTOK*DM]; // act lo
static __device__ __nv_bfloat16 g_wh[4*DM*DM];   // W^T hi [N,K] x {Wq,Wk,Wv,Wo}
static __device__ __nv_bfloat16 g_wl[4*DM*DM];   // W^T lo
static __device__ __nv_bfloat16 g_qh[MTOK*DM];   // q  [B,H,S,Dh]
static __device__ __nv_bfloat16 g_ql[MTOK*DM];
static __device__ __nv_bfloat16 g_kh[MTOK*DM];   // k  [B,H,S,Dh]
static __device__ __nv_bfloat16 g_kl[MTOK*DM];
static __device__ __nv_bfloat16 g_vh[MTOK*DM];   // v  [B,H,Dh,S] (transposed)
static __device__ __nv_bfloat16 g_vl[MTOK*DM];

// ---------------------------------------------------------------------------
// helpers (arch-generic PTX only: ldmatrix / mma.sync / cp.async)
// ---------------------------------------------------------------------------
__device__ __forceinline__ uint32_t smem_u32(const void* p) {
    uint32_t a;
    asm("{ .reg .u64 t; cvta.to.shared.u64 t, %1; cvt.u32.u64 %0, t; }"
        : "=r"(a) : "l"(p));
    return a;
}
__device__ __forceinline__ void ldm_x4(uint32_t* r, uint32_t addr) {
    asm volatile("ldmatrix.sync.aligned.m8n8.x4.shared.b16 {%0,%1,%2,%3}, [%4];"
                 : "=r"(r[0]), "=r"(r[1]), "=r"(r[2]), "=r"(r[3]) : "r"(addr));
}
__device__ __forceinline__ void mma_bf16(float* d, const uint32_t* a,
                                         const uint32_t* b) {
    asm volatile(
        "mma.sync.aligned.m16n8k16.row.col.f32.bf16.bf16.f32 "
        "{%0,%1,%2,%3}, {%4,%5,%6,%7}, {%8,%9}, {%0,%1,%2,%3};"
        : "+f"(d[0]), "+f"(d[1]), "+f"(d[2]), "+f"(d[3])
        : "r"(a[0]), "r"(a[1]), "r"(a[2]), "r"(a[3]), "r"(b[0]), "r"(b[1]));
}
__device__ __forceinline__ void cp16(uint32_t dst, const void* src) {
    asm volatile("cp.async.cg.shared.global [%0], [%1], 16;"
                 :: "r"(dst), "l"(src));
}
#define CP_COMMIT() asm volatile("cp.async.commit_group;" ::: "memory")
#define CP_WAIT(n)  asm volatile("cp.async.wait_group %0;" :: "n"(n) : "memory")

__device__ __forceinline__ uint32_t pack_bf16(float lo, float hi) {
    uint32_t r;
    asm("cvt.rn.bf16x2.f32 %0, %1, %2;" : "=r"(r) : "f"(hi), "f"(lo));
    return r;
}
__device__ __forceinline__ float bf16_round(float v) {
    return __bfloat162float(__float2bfloat16(v));
}

// ---------------------------------------------------------------------------
// Fused split: fp32 activations {Q,K,V} -> bf16 hi/lo regions (blockIdx.y)
// ---------------------------------------------------------------------------
__global__ void __launch_bounds__(256) split_act3_kernel(
    const float* __restrict__ x0, const float* __restrict__ x1,
    const float* __restrict__ x2,
    __nv_bfloat16* __restrict__ xh, __nv_bfloat16* __restrict__ xl)
{
    const int z = blockIdx.y;
    const float* x = (z == 0) ? x0 : (z == 1) ? x1 : x2;
    const size_t off = (size_t)z * MTOK * DM / 4;   // float4 units
    const size_t li = blockIdx.x * blockDim.x + threadIdx.x;
    const size_t i  = off + li;
    float4 v = ((const float4*)x)[li];
    float a[4] = {v.x, v.y, v.z, v.w};
    __nv_bfloat162 h01, h23, l01, l23;
    __nv_bfloat16 h0 = __float2bfloat16(a[0]);
    __nv_bfloat16 h1 = __float2bfloat16(a[1]);
    __nv_bfloat16 h2 = __float2bfloat16(a[2]);
    __nv_bfloat16 h3 = __float2bfloat16(a[3]);
    h01.x = h0; h01.y = h1; h23.x = h2; h23.y = h3;
    l01.x = __float2bfloat16(a[0] - __bfloat162float(h0));
    l01.y = __float2bfloat16(a[1] - __bfloat162float(h1));
    l23.x = __float2bfloat16(a[2] - __bfloat162float(h2));
    l23.y = __float2bfloat16(a[3] - __bfloat162float(h3));
    ((__nv_bfloat162*)xh)[2*i]   = h01;
    ((__nv_bfloat162*)xh)[2*i+1] = h23;
    ((__nv_bfloat162*)xl)[2*i]   = l01;
    ((__nv_bfloat162*)xl)[2*i+1] = l23;
}

// ---------------------------------------------------------------------------
// Fused transpose+split of all 4 weights (blockIdx.z): W[k][n] -> wh/wl[n][k]
// ---------------------------------------------------------------------------
__global__ void __launch_bounds__(256) trans_split4_kernel(
    const float* __restrict__ W0, const float* __restrict__ W1,
    const float* __restrict__ W2, const float* __restrict__ W3,
    __nv_bfloat16* __restrict__ wh, __nv_bfloat16* __restrict__ wl)
{
    __shared__ float t[32][33];
    const int z = blockIdx.z;
    const float* W = (z == 0) ? W0 : (z == 1) ? W1 : (z == 2) ? W2 : W3;
    const size_t zo = (size_t)z * DM * DM;
    const int k0 = blockIdx.y * 32, n0 = blockIdx.x * 32;
    const int tx = threadIdx.x, ty = threadIdx.y;     // (32, 8)
    #pragma unroll
    for (int j = 0; j < 4; j++)
        t[ty + j*8][tx] = W[(size_t)(k0 + ty + j*8) * DM + n0 + tx];
    __syncthreads();
    #pragma unroll
    for (int j = 0; j < 4; j++) {
        int nn = ty + j*8;
        float v = t[tx][nn];                           // = W[k0+tx][n0+nn]
        __nv_bfloat16 h = __float2bfloat16(v);
        size_t idx = zo + (size_t)(n0 + nn) * DM + k0 + tx;
        wh[idx] = h;
        wl[idx] = __float2bfloat16(v - __bfloat162float(h));
    }
}

// ---------------------------------------------------------------------------
// GEMM geometry: R10-proven (BM128/BN128/BK32, 2-stage, 2 CTAs/SM).
// R13: single barrier per chunk (issue moved after the barrier; CP_WAIT(0)
// + barrier makes chunk-c data visible; iter-c barrier fences iter c-1's
// stage (c+1)&1 readers before the overwrite) + staggered LDSM batches
// (each load batch overlaps the prior mma batch's pipe drain).
// ---------------------------------------------------------------------------
#define BM 128
#define BN 128
#define BK 32
#define STR 40
#define TILE_ELEMS (BM * STR)
#define STAGE_ELEMS (4 * TILE_ELEMS)
#define GEMM_SMEM (2 * STAGE_ELEMS * 2)       // 81920 B
#define NCHUNK (DM / BK)                      // 32
#define TSTR 132                              // fp32 transpose stride (MODE 2)

// mainloop body shared textually by the kernels below (kept verbatim per
// kernel so each gets its own register allocation).

// ---------------------------------------------------------------------------
// Fused Q+K projection: blockIdx.z in {0,1}; BOTH use the MODE-1 epilogue.
// ---------------------------------------------------------------------------
__global__ void __launch_bounds__(256, 2) gemm_qk_kernel(
    const __nv_bfloat16* __restrict__ Ah0, const __nv_bfloat16* __restrict__ Al0,
    const __nv_bfloat16* __restrict__ Ah1, const __nv_bfloat16* __restrict__ Al1,
    const __nv_bfloat16* __restrict__ Wh,  const __nv_bfloat16* __restrict__ Wl,
    const float* __restrict__ bq, const float* __restrict__ bk,
    __nv_bfloat16* __restrict__ qh, __nv_bfloat16* __restrict__ ql,
    __nv_bfloat16* __restrict__ kh, __nv_bfloat16* __restrict__ kl)
{
    extern __shared__ __nv_bfloat16 sm[];
    const uint32_t sbase = smem_u32(sm);

    const int tid  = threadIdx.x;
    const int lane = tid & 31;
    const int wid  = tid >> 5;
    const int wm   = (wid >> 2) * 64;
    const int wn   = (wid & 3) * 32;
    const int bm   = blockIdx.y * BM;
    const int bn   = blockIdx.x * BN;
    const int z    = blockIdx.z;

    const __nv_bfloat16* Ah = z ? Ah1 : Ah0;
    const __nv_bfloat16* Al = z ? Al1 : Al0;
    const __nv_bfloat16* Bh = Wh + (size_t)z * DM * DM;
    const __nv_bfloat16* Bl = Wl + (size_t)z * DM * DM;
    const float* bias = z ? bk : bq;
    __nv_bfloat16* Ch = z ? kh : qh;
    __nv_bfloat16* Cl = z ? kl : ql;

    float acc[4][4][4];
    #pragma unroll
    for (int i = 0; i < 4; i++)
        #pragma unroll
        for (int j = 0; j < 4; j++)
            #pragma unroll
            for (int c = 0; c < 4; c++) acc[i][j][c] = 0.f;

    const int a_r  = wm + (lane & 7) + ((lane >> 3) & 1) * 8;
    const int a_k  = (lane >> 4) * 8;
    const int b_r  = wn + (lane & 7) + (lane >> 4) * 8;
    const int b_k  = ((lane >> 3) & 1) * 8;

    auto issue_chunk = [&](int c, int stg) {
        const int k0 = c * BK;
        const uint32_t sA = sbase + (uint32_t)(stg * STAGE_ELEMS) * 2;
        #pragma unroll
        for (int i = 0; i < 2; i++) {
            int t = tid + i * 256;
            int r = t >> 2, cc = (t & 3) * 8;
            uint32_t so = (uint32_t)(r * STR + cc) * 2;
            size_t ga = (size_t)(bm + r) * DM + k0 + cc;
            size_t gb = (size_t)(bn + r) * DM + k0 + cc;
            cp16(sA + so,                      Ah + ga);
            cp16(sA + TILE_ELEMS*2 + so,       Al + ga);
            cp16(sA + 2*TILE_ELEMS*2 + so,     Bh + gb);
            cp16(sA + 3*TILE_ELEMS*2 + so,     Bl + gb);
        }
        CP_COMMIT();
    };

    issue_chunk(0, 0);

    for (int c = 0; c < NCHUNK; c++) {
        CP_WAIT(0);
        __syncthreads();                       // single barrier per chunk
        if (c + 1 < NCHUNK) issue_chunk(c + 1, (c + 1) & 1);

        const uint32_t sA  = sbase + (uint32_t)((c & 1) * STAGE_ELEMS) * 2;
        const uint32_t sAl = sA + TILE_ELEMS * 2;
        const uint32_t sB  = sA + 2 * TILE_ELEMS * 2;
        const uint32_t sBl = sA + 3 * TILE_ELEMS * 2;

        #pragma unroll
        for (int ks = 0; ks < BK / 16; ks++) {
            uint32_t ra[4][4], rbh[2][4], rbl[2][4];
            #pragma unroll
            for (int mi = 0; mi < 4; mi++)
                ldm_x4(ra[mi], sA + (uint32_t)((a_r + mi*16) * STR + ks*16 + a_k) * 2);
            #pragma unroll
            for (int n2 = 0; n2 < 2; n2++)
                ldm_x4(rbh[n2], sB + (uint32_t)((b_r + n2*16) * STR + ks*16 + b_k) * 2);
            #pragma unroll
            for (int mi = 0; mi < 4; mi++)
                #pragma unroll
                for (int ni = 0; ni < 4; ni++)
                    mma_bf16(acc[mi][ni], ra[mi], &rbh[ni >> 1][(ni & 1) * 2]);
            #pragma unroll
            for (int n2 = 0; n2 < 2; n2++)
                ldm_x4(rbl[n2], sBl + (uint32_t)((b_r + n2*16) * STR + ks*16 + b_k) * 2);
            #pragma unroll
            for (int mi = 0; mi < 4; mi++)
                #pragma unroll
                for (int ni = 0; ni < 4; ni++)
                    mma_bf16(acc[mi][ni], ra[mi], &rbl[ni >> 1][(ni & 1) * 2]);
            #pragma unroll
            for (int mi = 0; mi < 4; mi++)
                ldm_x4(ra[mi], sAl + (uint32_t)((a_r + mi*16) * STR + ks*16 + a_k) * 2);
            #pragma unroll
            for (int mi = 0; mi < 4; mi++)
                #pragma unroll
                for (int ni = 0; ni < 4; ni++)
                    mma_bf16(acc[mi][ni], ra[mi], &rbh[ni >> 1][(ni & 1) * 2]);
        }
        __syncthreads();                       // compute done before next overwrite
    }

    const int er = lane >> 2;
    const int ec = (lane & 3) * 2;
    #pragma unroll
    for (int mi = 0; mi < 4; mi++) {
        #pragma unroll
        for (int ni = 0; ni < 4; ni++) {
            const int n  = bn + wn + ni * 8 + ec;
            const float b0 = bias[n], b1 = bias[n + 1];
            #pragma unroll
            for (int half = 0; half < 2; half++) {
                const int m = bm + wm + mi * 16 + er + half * 8;
                float v0 = acc[mi][ni][half * 2 + 0] + b0;
                float v1 = acc[mi][ni][half * 2 + 1] + b1;
                float h0 = bf16_round(v0), h1 = bf16_round(v1);
                const int b_ = m >> 11;
                const int s  = m & (SEQ - 1);
                const int h  = n >> 6;
                const int d  = n & (HD - 1);
                size_t idx = ((((size_t)b_ * NH + h) * SEQ) + s) * HD + d;
                *(uint32_t*)&Ch[idx] = pack_bf16(h0, h1);
                *(uint32_t*)&Cl[idx] = pack_bf16(v0 - h0, v1 - h1);
            }
        }
    }
}

// ---------------------------------------------------------------------------
// Templated GEMM for V (MODE 2) and O (MODE 0).
// ---------------------------------------------------------------------------
template<int MODE>
__global__ void __launch_bounds__(256, 2) gemm_mma_kernel(
    const __nv_bfloat16* __restrict__ Ah, const __nv_bfloat16* __restrict__ Al,
    const __nv_bfloat16* __restrict__ Bh, const __nv_bfloat16* __restrict__ Bl,
    const float* __restrict__ bias, float* __restrict__ Cf,
    __nv_bfloat16* __restrict__ Ch, __nv_bfloat16* __restrict__ Cl)
{
    extern __shared__ __nv_bfloat16 sm[];
    const uint32_t sbase = smem_u32(sm);

    const int tid  = threadIdx.x;
    const int lane = tid & 31;
    const int wid  = tid >> 5;
    const int wm   = (wid >> 2) * 64;
    const int wn   = (wid & 3) * 32;
    const int bm   = blockIdx.y * BM;
    const int bn   = blockIdx.x * BN;

    float acc[4][4][4];
    #pragma unroll
    for (int i = 0; i < 4; i++)
        #pragma unroll
        for (int j = 0; j < 4; j++)
            #pragma unroll
            for (int c = 0; c < 4; c++) acc[i][j][c] = 0.f;

    const int a_r  = wm + (lane & 7) + ((lane >> 3) & 1) * 8;
    const int a_k  = (lane >> 4) * 8;
    const int b_r  = wn + (lane & 7) + (lane >> 4) * 8;
    const int b_k  = ((lane >> 3) & 1) * 8;

    auto issue_chunk = [&](int c, int stg) {
        const int k0 = c * BK;
        const uint32_t sA = sbase + (uint32_t)(stg * STAGE_ELEMS) * 2;
        #pragma unroll
        for (int i = 0; i < 2; i++) {
            int t = tid + i * 256;
            int r = t >> 2, cc = (t & 3) * 8;
            uint32_t so = (uint32_t)(r * STR + cc) * 2;
            size_t ga = (size_t)(bm + r) * DM + k0 + cc;
            size_t gb = (size_t)(bn + r) * DM + k0 + cc;
            cp16(sA + so,                      Ah + ga);
            cp16(sA + TILE_ELEMS*2 + so,       Al + ga);
            cp16(sA + 2*TILE_ELEMS*2 + so,     Bh + gb);
            cp16(sA + 3*TILE_ELEMS*2 + so,     Bl + gb);
        }
        CP_COMMIT();
    };

    issue_chunk(0, 0);

    for (int c = 0; c < NCHUNK; c++) {
        CP_WAIT(0);
        __syncthreads();                       // single barrier per chunk
        if (c + 1 < NCHUNK) issue_chunk(c + 1, (c + 1) & 1);

        const uint32_t sA  = sbase + (uint32_t)((c & 1) * STAGE_ELEMS) * 2;
        const uint32_t sAl = sA + TILE_ELEMS * 2;
        const uint32_t sB  = sA + 2 * TILE_ELEMS * 2;
        const uint32_t sBl = sA + 3 * TILE_ELEMS * 2;

        #pragma unroll
        for (int ks = 0; ks < BK / 16; ks++) {
            uint32_t ra[4][4], rbh[2][4], rbl[2][4];
            #pragma unroll
            for (int mi = 0; mi < 4; mi++)
                ldm_x4(ra[mi], sA + (uint32_t)((a_r + mi*16) * STR + ks*16 + a_k) * 2);
            #pragma unroll
            for (int n2 = 0; n2 < 2; n2++)
                ldm_x4(rbh[n2], sB + (uint32_t)((b_r + n2*16) * STR + ks*16 + b_k) * 2);
            #pragma unroll
            for (int mi = 0; mi < 4; mi++)
                #pragma unroll
                for (int ni = 0; ni < 4; ni++)
                    mma_bf16(acc[mi][ni], ra[mi], &rbh[ni >> 1][(ni & 1) * 2]);
            #pragma unroll
            for (int n2 = 0; n2 < 2; n2++)
                ldm_x4(rbl[n2], sBl + (uint32_t)((b_r + n2*16) * STR + ks*16 + b_k) * 2);
            #pragma unroll
            for (int mi = 0; mi < 4; mi++)
                #pragma unroll
                for (int ni = 0; ni < 4; ni++)
                    mma_bf16(acc[mi][ni], ra[mi], &rbl[ni >> 1][(ni & 1) * 2]);
            #pragma unroll
            for (int mi = 0; mi < 4; mi++)
                ldm_x4(ra[mi], sAl + (uint32_t)((a_r + mi*16) * STR + ks*16 + a_k) * 2);
            #pragma unroll
            for (int mi = 0; mi < 4; mi++)
                #pragma unroll
                for (int ni = 0; ni < 4; ni++)
                    mma_bf16(acc[mi][ni], ra[mi], &rbh[ni >> 1][(ni & 1) * 2]);
        }
        __syncthreads();                       // compute done before next overwrite
    }

    const int er = lane >> 2;
    const int ec = (lane & 3) * 2;

    if (MODE == 2) {
        // smem-transposed epilogue: coalesced writes to [B,H,Dh,S]
        float* smf = (float*)sm;           // 128 x TSTR fp32 (67584 B < 81920)
        #pragma unroll
        for (int mi = 0; mi < 4; mi++)
            #pragma unroll
            for (int ni = 0; ni < 4; ni++) {
                const int n = wn + ni * 8 + ec;
                const float b0 = bias[bn + n], b1 = bias[bn + n + 1];
                #pragma unroll
                for (int half = 0; half < 2; half++) {
                    const int m = wm + mi * 16 + er + half * 8;
                    smf[(n)     * TSTR + m] = acc[mi][ni][half * 2 + 0] + b0;
                    smf[(n + 1) * TSTR + m] = acc[mi][ni][half * 2 + 1] + b1;
                }
            }
        __syncthreads();
        const int b_ = bm >> 11;
        #pragma unroll
        for (int i = 0; i < 16; i++) {
            const int n  = wid * 16 + i;           // local col 0..127
            const int gn = bn + n;
            const int h  = gn >> 6, d = gn & 63;
            float4 v = *(const float4*)&smf[n * TSTR + lane * 4];
            float h0 = bf16_round(v.x), h1 = bf16_round(v.y);
            float h2 = bf16_round(v.z), h3 = bf16_round(v.w);
            size_t base = (((size_t)b_ * NH + h) * HD + d) * SEQ
                        + (bm & (SEQ - 1)) + lane * 4;
            *(uint32_t*)&Ch[base]     = pack_bf16(h0, h1);
            *(uint32_t*)&Ch[base + 2] = pack_bf16(h2, h3);
            *(uint32_t*)&Cl[base]     = pack_bf16(v.x - h0, v.y - h1);
            *(uint32_t*)&Cl[base + 2] = pack_bf16(v.z - h2, v.w - h3);
        }
        return;
    }

    #pragma unroll
    for (int mi = 0; mi < 4; mi++) {
        #pragma unroll
        for (int ni = 0; ni < 4; ni++) {
            const int n  = bn + wn + ni * 8 + ec;
            const float b0 = bias[n], b1 = bias[n + 1];
            #pragma unroll
            for (int half = 0; half < 2; half++) {
                const int m = bm + wm + mi * 16 + er + half * 8;
                float2 o;
                o.x = acc[mi][ni][half * 2 + 0] + b0;
                o.y = acc[mi][ni][half * 2 + 1] + b1;
                *(float2*)&Cf[(size_t)m * DM + n] = o;
            }
        }
    }
}

// ---------------------------------------------------------------------------
// Tensor-core flash attention, split bf16 (3-pass per GEMM).
// CTA: 64 queries of one (b,h); 128 thr / 4 warps; warp = 16 rows.
// K double-buffered, V single-buffered; 72KB smem; FORCED 3 CTAs/SM.
// (R8-R12 measured: 282us, regs=157, tensor=59.9% -- unchanged this round.)
// ---------------------------------------------------------------------------
#define ASTR 72
#define ATILE (64 * ASTR)                     // 4608 bf16 elems
#define ATT_SMEM (8 * ATILE * 2)              // 73728 B

__global__ void __launch_bounds__(128, 3) attn_mma_kernel(
    const __nv_bfloat16* __restrict__ qh, const __nv_bfloat16* __restrict__ ql,
    const __nv_bfloat16* __restrict__ kh, const __nv_bfloat16* __restrict__ kl,
    const __nv_bfloat16* __restrict__ vh, const __nv_bfloat16* __restrict__ vl,
    __nv_bfloat16* __restrict__ oh, __nv_bfloat16* __restrict__ ol)
{
    extern __shared__ __nv_bfloat16 smA[];
    const uint32_t sb  = smem_u32(smA);
    const int tid  = threadIdx.x;
    const int lane = tid & 31;
    const int w    = tid >> 5;
    const int bh   = blockIdx.y;              // b*NH + h
    const int q0   = blockIdx.x * 64;
    const size_t bo = (size_t)bh * SEQ * HD;

    const uint32_t sQh = sb;
    const uint32_t sQl = sb + ATILE * 2;
    const uint32_t sVh = sb + 6 * ATILE * 2;
    const uint32_t sVl = sb + 7 * ATILE * 2;

    auto issue_K = [&](int t, int stg) {
        const int c0 = t * 64;
        const uint32_t base = sb + (uint32_t)(2 + 2 * stg) * ATILE * 2;
        const __nv_bfloat16* gkh = kh + bo + (size_t)c0 * HD;
        const __nv_bfloat16* gkl = kl + bo + (size_t)c0 * HD;
        #pragma unroll
        for (int i = 0; i < 4; i++) {
            int e = tid + i * 128;
            int r = e >> 3, c8 = (e & 7) * 8;
            uint32_t so = (uint32_t)(r * ASTR + c8) * 2;
            cp16(base + so,             gkh + r * HD + c8);
            cp16(base + ATILE*2 + so,   gkl + r * HD + c8);
        }
    };
    auto issue_V = [&](int t) {
        const int c0 = t * 64;
        const __nv_bfloat16* gvh = vh + bo + c0;
        const __nv_bfloat16* gvl = vl + bo + c0;
        #pragma unroll
        for (int i = 0; i < 4; i++) {
            int e = tid + i * 128;
            int r = e >> 3, c8 = (e & 7) * 8;
            uint32_t so = (uint32_t)(r * ASTR + c8) * 2;
            cp16(sVh + so, gvh + (size_t)r * SEQ + c8);
            cp16(sVl + so, gvl + (size_t)r * SEQ + c8);
        }
    };

    // prologue: G0 = {Q, K0}, G1 = {V0}
    {
        const __nv_bfloat16* gqh = qh + bo + (size_t)q0 * HD;
        const __nv_bfloat16* gql = ql + bo + (size_t)q0 * HD;
        #pragma unroll
        for (int i = 0; i < 4; i++) {
            int e = tid + i * 128;
            int r = e >> 3, c8 = (e & 7) * 8;
            uint32_t so = (uint32_t)(r * ASTR + c8) * 2;
            cp16(sQh + so, gqh + r * HD + c8);
            cp16(sQl + so, gql + r * HD + c8);
        }
        issue_K(0, 0);
        CP_COMMIT();
        issue_V(0);
        CP_COMMIT();
    }

    const int a_r = w * 16 + (lane & 7) + ((lane >> 3) & 1) * 8;
    const int a_k = (lane >> 4) * 8;
    const int b_r = (lane & 7) + (lane >> 4) * 8;
    const int b_k = ((lane >> 3) & 1) * 8;

    uint32_t qfh[4][4];
    float m_i[2] = {-1e30f, -1e30f}, l_i[2] = {0.f, 0.f};
    float accO[8][4];
    #pragma unroll
    for (int j = 0; j < 8; j++)
        #pragma unroll
        for (int c = 0; c < 4; c++) accO[j][c] = 0.f;

    for (int t = 0; t < SEQ / 64; t++) {
        if (t + 1 < SEQ / 64) { issue_K(t + 1, (t + 1) & 1); CP_COMMIT(); }
        if (t + 1 < SEQ / 64) { CP_WAIT(2); } else { CP_WAIT(1); }
        __syncthreads();                       // sync_K

        if (t == 0) {
            #pragma unroll
            for (int ks = 0; ks < 4; ks++)
                ldm_x4(qfh[ks], sQh + (uint32_t)(a_r * ASTR + ks*16 + a_k) * 2);
        }

        const uint32_t sK  = sb + (uint32_t)(2 + 2 * (t & 1)) * ATILE * 2;
        const uint32_t sKl = sK + ATILE * 2;

        // ---- scores: S = Qh Kh^T + Qh Kl^T + Ql Kh^T -------------------
        float accS[8][4];
        #pragma unroll
        for (int j = 0; j < 8; j++)
            #pragma unroll
            for (int c = 0; c < 4; c++) accS[j][c] = 0.f;

        #pragma unroll
        for (int ks = 0; ks < 4; ks++) {
            uint32_t qfl[4], bhf[4][4], blf[4][4];
            ldm_x4(qfl, sQl + (uint32_t)(a_r * ASTR + ks*16 + a_k) * 2);
            #pragma unroll
            for (int n2 = 0; n2 < 4; n2++) {
                ldm_x4(bhf[n2], sK  + (uint32_t)((b_r + n2*16) * ASTR + ks*16 + b_k) * 2);
                ldm_x4(blf[n2], sKl + (uint32_t)((b_r + n2*16) * ASTR + ks*16 + b_k) * 2);
            }
            #pragma unroll
            for (int j = 0; j < 8; j++)
                mma_bf16(accS[j], qfh[ks], &bhf[j >> 1][(j & 1) * 2]);
            #pragma unroll
            for (int j = 0; j < 8; j++)
                mma_bf16(accS[j], qfh[ks], &blf[j >> 1][(j & 1) * 2]);
            #pragma unroll
            for (int j = 0; j < 8; j++)
                mma_bf16(accS[j], qfl, &bhf[j >> 1][(j & 1) * 2]);
        }

        // ---- online softmax, both row-halves phase-parallel ------------
        #pragma unroll
        for (int j = 0; j < 8; j++)
            #pragma unroll
            for (int c = 0; c < 4; c++) accS[j][c] *= 0.125f;

        float mx0 = -1e30f, mx1 = -1e30f;
        #pragma unroll
        for (int j = 0; j < 8; j++) {
            mx0 = fmaxf(mx0, fmaxf(accS[j][0], accS[j][1]));
            mx1 = fmaxf(mx1, fmaxf(accS[j][2], accS[j][3]));
        }
        mx0 = fmaxf(mx0, __shfl_xor_sync(0xffffffffu, mx0, 1));
        mx1 = fmaxf(mx1, __shfl_xor_sync(0xffffffffu, mx1, 1));
        mx0 = fmaxf(mx0, __shfl_xor_sync(0xffffffffu, mx0, 2));
        mx1 = fmaxf(mx1, __shfl_xor_sync(0xffffffffu, mx1, 2));
        const float mn0 = fmaxf(m_i[0], mx0), mn1 = fmaxf(m_i[1], mx1);
        const float al0 = __expf(m_i[0] - mn0), al1 = __expf(m_i[1] - mn1);
        m_i[0] = mn0; m_i[1] = mn1;
        float s0 = 0.f, s1 = 0.f;
        #pragma unroll
        for (int j = 0; j < 8; j++) {
            float p0 = __expf(accS[j][0] - mn0);
            float p1 = __expf(accS[j][1] - mn0);
            float p2 = __expf(accS[j][2] - mn1);
            float p3 = __expf(accS[j][3] - mn1);
            accS[j][0] = p0; accS[j][1] = p1; accS[j][2] = p2; accS[j][3] = p3;
            s0 += p0 + p1; s1 += p2 + p3;
        }
        s0 += __shfl_xor_sync(0xffffffffu, s0, 1);
        s1 += __shfl_xor_sync(0xffffffffu, s1, 1);
        s0 += __shfl_xor_sync(0xffffffffu, s0, 2);
        s1 += __shfl_xor_sync(0xffffffffu, s1, 2);
        l_i[0] = l_i[0] * al0 + s0;
        l_i[1] = l_i[1] * al1 + s1;
        #pragma unroll
        for (int j = 0; j < 8; j++) {
            accO[j][0] *= al0; accO[j][1] *= al0;
            accO[j][2] *= al1; accO[j][3] *= al1;
        }

        // ---- P -> A-fragments, split bf16 ------------------------------
        uint32_t pah[4][4], pal[4][4];
        #pragma unroll
        for (int ks = 0; ks < 4; ks++) {
            const int j0 = 2*ks, j1 = j0 + 1;
            #pragma unroll
            for (int q = 0; q < 4; q++) {
                const int jj = (q < 2) ? j0 : j1;
                const int c0 = (q & 1) * 2;
                float v0 = accS[jj][c0], v1 = accS[jj][c0 + 1];
                float h0 = bf16_round(v0), h1 = bf16_round(v1);
                pah[ks][q] = pack_bf16(h0, h1);
                pal[ks][q] = pack_bf16(v0 - h0, v1 - h1);
            }
        }

        if (t + 1 < SEQ / 64) { CP_WAIT(1); } else { CP_WAIT(0); }
        __syncthreads();                       // sync_V

        // ---- O += Ph Vh + Ph Vl + Pl Vh --------------------------------
        #pragma unroll
        for (int ks = 0; ks < 4; ks++) {
            uint32_t bvh[4][4], bvl[4][4];
            #pragma unroll
            for (int n2 = 0; n2 < 4; n2++) {
                ldm_x4(bvh[n2], sVh + (uint32_t)((b_r + n2*16) * ASTR + ks*16 + b_k) * 2);
                ldm_x4(bvl[n2], sVl + (uint32_t)((b_r + n2*16) * ASTR + ks*16 + b_k) * 2);
            }
            #pragma unroll
            for (int j = 0; j < 8; j++)
                mma_bf16(accO[j], pah[ks], &bvh[j >> 1][(j & 1) * 2]);
            #pragma unroll
            for (int j = 0; j < 8; j++)
                mma_bf16(accO[j], pah[ks], &bvl[j >> 1][(j & 1) * 2]);
            #pragma unroll
            for (int j = 0; j < 8; j++)
                mma_bf16(accO[j], pal[ks], &bvh[j >> 1][(j & 1) * 2]);
        }
        __syncthreads();                       // sync_end: V reads done

        if (t + 1 < SEQ / 64) { issue_V(t + 1); CP_COMMIT(); }
    }

    // ---- epilogue: normalize, split, write [B,S,DM] bf16 hi/lo ---------
    const int b_  = bh >> 4, hh_ = bh & 15;
    const int er  = lane >> 2, ec = (lane & 3) * 2;
    #pragma unroll
    for (int hh = 0; hh < 2; hh++) {
        const float inv = 1.f / l_i[hh];
        const int m = q0 + w * 16 + er + hh * 8;
        const size_t rowbase = ((size_t)(b_ * SEQ + m)) * DM + hh_ * HD;
        #pragma unroll
        for (int j = 0; j < 8; j++) {
            float o0 = accO[j][hh*2]   * inv;
            float o1 = accO[j][hh*2+1] * inv;
            float h0 = bf16_round(o0), h1 = bf16_round(o1);
            *(uint32_t*)&oh[rowbase + j*8 + ec] = pack_bf16(h0, h1);
            *(uint32_t*)&ol[rowbase + j*8 + ec] = pack_bf16(o0 - h0, o1 - h1);
        }
    }
}

// ---------------------------------------------------------------------------
extern "C" void kernel_launch(void* const* d_in, const int* in_sizes, int n_in,
                              void* d_out, int out_size)
{
    const float* Q  = (const float*)d_in[0];
    const float* K  = (const float*)d_in[1];
    const float* V  = (const float*)d_in[2];
    const float* Wq = (const float*)d_in[3];
    const float* bq = (const float*)d_in[4];
    const float* Wk = (const float*)d_in[5];
    const float* bk = (const float*)d_in[6];
    const float* Wv = (const float*)d_in[7];
    const float* bv = (const float*)d_in[8];
    const float* Wo = (const float*)d_in[9];
    const float* bo = (const float*)d_in[10];
    float* out = (float*)d_out;

    __nv_bfloat16 *ah, *al, *wh, *wl, *qh, *ql, *kh, *kl, *vh, *vl;
    cudaGetSymbolAddress((void**)&ah, g_ah);
    cudaGetSymbolAddress((void**)&al, g_al);
    cudaGetSymbolAddress((void**)&wh, g_wh);
    cudaGetSymbolAddress((void**)&wl, g_wl);
    cudaGetSymbolAddress((void**)&qh, g_qh);
    cudaGetSymbolAddress((void**)&ql, g_ql);
    cudaGetSymbolAddress((void**)&kh, g_kh);
    cudaGetSymbolAddress((void**)&kl, g_kl);
    cudaGetSymbolAddress((void**)&vh, g_vh);
    cudaGetSymbolAddress((void**)&vl, g_vl);

    cudaFuncSetAttribute(gemm_qk_kernel,
                         cudaFuncAttributeMaxDynamicSharedMemorySize, GEMM_SMEM);
    cudaFuncSetAttribute(gemm_mma_kernel<0>,
                         cudaFuncAttributeMaxDynamicSharedMemorySize, GEMM_SMEM);
    cudaFuncSetAttribute(gemm_mma_kernel<2>,
                         cudaFuncAttributeMaxDynamicSharedMemorySize, GEMM_SMEM);
    cudaFuncSetAttribute(attn_mma_kernel,
                         cudaFuncAttributeMaxDynamicSharedMemorySize, ATT_SMEM);

    // 1. split Q,K,V activations (one launch)
    const dim3 gridS(MTOK * DM / 4 / 256, 3);
    split_act3_kernel<<<gridS, 256>>>(Q, K, V, ah, al);

    // 2. transpose+split all 4 weights (one launch)
    const dim3 gridT(DM / 32, DM / 32, 4), blkT(32, 8);
    trans_split4_kernel<<<gridT, blkT>>>(Wq, Wk, Wv, Wo, wh, wl);

    // 3a. fused Q+K projections (one launch, 512 CTAs, uniform MODE-1 epilogue)
    const size_t AZ = (size_t)MTOK * DM, WZ = (size_t)DM * DM;
    const dim3 gridQK(DM / BN, MTOK / BM, 2);   // (8, 32, 2)
    gemm_qk_kernel<<<gridQK, 256, GEMM_SMEM>>>(ah, al, ah + AZ, al + AZ,
                                               wh, wl, bq, bk,
                                               qh, ql, kh, kl);

    // 3b. V projection (MODE 2, transposed epilogue)
    const dim3 gridG(DM / BN, MTOK / BM);       // (8, 32)
    gemm_mma_kernel<2><<<gridG, 256, GEMM_SMEM>>>(ah + 2*AZ, al + 2*AZ,
                                                  wh + 2*WZ, wl + 2*WZ, bv,
                                                  nullptr, vh, vl);

    // 4. tensor-core attention -> split bf16 [B,S,DM] into ah/al (z=0 region)
    const dim3 gridA(SEQ / 64, BATCH * NH);
    attn_mma_kernel<<<gridA, 128, ATT_SMEM>>>(qh, ql, kh, kl, vh, vl, ah, al);

    // 5. output projection -> fp32 d_out
    gemm_mma_kernel<0><<<gridG, 256, GEMM_SMEM>>>(ah, al,
                                                  wh + 3*WZ, wl + 3*WZ, bo,
                                                  out, nullptr, nullptr);
}

// round 16
// speedup vs baseline: 1.0156x; 1.0156x over previous
#include <cuda_runtime.h>
#include <cuda_bf16.h>
#include <cstdint>

#define DM   1024
#define NH   16
#define HD   64
#define BATCH 2
#define SEQ  2048
#define MTOK (BATCH*SEQ)   // 4096

// ---------------------------------------------------------------------------
// Scratch (allocation-free rule: __device__ globals)
// ---------------------------------------------------------------------------
static __device__ __nv_bfloat16 g_ah[3*MTOK*DM]; // act hi: z=0 Q / attn-out, z=1 K, z=2 V
static __device__ __nv_bfloat16 g_al[3*MTOK*DM]; // act lo
static __device__ __nv_bfloat16 g_wh[4*DM*DM];   // W^T hi [N,K] x {Wq,Wk,Wv,Wo}
static __device__ __nv_bfloat16 g_wl[4*DM*DM];   // W^T lo
static __device__ __nv_bfloat16 g_qh[MTOK*DM];   // q  [B,H,S,Dh]
static __device__ __nv_bfloat16 g_ql[MTOK*DM];
static __device__ __nv_bfloat16 g_kh[MTOK*DM];   // k  [B,H,S,Dh]
static __device__ __nv_bfloat16 g_kl[MTOK*DM];
static __device__ __nv_bfloat16 g_vh[MTOK*DM];   // v  [B,H,Dh,S] (transposed)
static __device__ __nv_bfloat16 g_vl[MTOK*DM];

// ---------------------------------------------------------------------------
// helpers (arch-generic PTX only: ldmatrix / mma.sync / cp.async)
// ---------------------------------------------------------------------------
__device__ __forceinline__ uint32_t smem_u32(const void* p) {
    uint32_t a;
    asm("{ .reg .u64 t; cvta.to.shared.u64 t, %1; cvt.u32.u64 %0, t; }"
        : "=r"(a) : "l"(p));
    return a;
}
__device__ __forceinline__ void ldm_x4(uint32_t* r, uint32_t addr) {
    asm volatile("ldmatrix.sync.aligned.m8n8.x4.shared.b16 {%0,%1,%2,%3}, [%4];"
                 : "=r"(r[0]), "=r"(r[1]), "=r"(r[2]), "=r"(r[3]) : "r"(addr));
}
__device__ __forceinline__ void mma_bf16(float* d, const uint32_t* a,
                                         const uint32_t* b) {
    asm volatile(
        "mma.sync.aligned.m16n8k16.row.col.f32.bf16.bf16.f32 "
        "{%0,%1,%2,%3}, {%4,%5,%6,%7}, {%8,%9}, {%0,%1,%2,%3};"
        : "+f"(d[0]), "+f"(d[1]), "+f"(d[2]), "+f"(d[3])
        : "r"(a[0]), "r"(a[1]), "r"(a[2]), "r"(a[3]), "r"(b[0]), "r"(b[1]));
}
__device__ __forceinline__ void cp16(uint32_t dst, const void* src) {
    asm volatile("cp.async.cg.shared.global [%0], [%1], 16;"
                 :: "r"(dst), "l"(src));
}
#define CP_COMMIT() asm volatile("cp.async.commit_group;" ::: "memory")
#define CP_WAIT(n)  asm volatile("cp.async.wait_group %0;" :: "n"(n) : "memory")

__device__ __forceinline__ uint32_t pack_bf16(float lo, float hi) {
    uint32_t r;
    asm("cvt.rn.bf16x2.f32 %0, %1, %2;" : "=r"(r) : "f"(hi), "f"(lo));
    return r;
}
__device__ __forceinline__ float bf16_round(float v) {
    return __bfloat162float(__float2bfloat16(v));
}

// ---------------------------------------------------------------------------
// Fused split: fp32 activations {Q,K,V} -> bf16 hi/lo regions (blockIdx.y)
// ---------------------------------------------------------------------------
__global__ void __launch_bounds__(256) split_act3_kernel(
    const float* __restrict__ x0, const float* __restrict__ x1,
    const float* __restrict__ x2,
    __nv_bfloat16* __restrict__ xh, __nv_bfloat16* __restrict__ xl)
{
    const int z = blockIdx.y;
    const float* x = (z == 0) ? x0 : (z == 1) ? x1 : x2;
    const size_t off = (size_t)z * MTOK * DM / 4;   // float4 units
    const size_t li = blockIdx.x * blockDim.x + threadIdx.x;
    const size_t i  = off + li;
    float4 v = ((const float4*)x)[li];
    float a[4] = {v.x, v.y, v.z, v.w};
    __nv_bfloat162 h01, h23, l01, l23;
    __nv_bfloat16 h0 = __float2bfloat16(a[0]);
    __nv_bfloat16 h1 = __float2bfloat16(a[1]);
    __nv_bfloat16 h2 = __float2bfloat16(a[2]);
    __nv_bfloat16 h3 = __float2bfloat16(a[3]);
    h01.x = h0; h01.y = h1; h23.x = h2; h23.y = h3;
    l01.x = __float2bfloat16(a[0] - __bfloat162float(h0));
    l01.y = __float2bfloat16(a[1] - __bfloat162float(h1));
    l23.x = __float2bfloat16(a[2] - __bfloat162float(h2));
    l23.y = __float2bfloat16(a[3] - __bfloat162float(h3));
    ((__nv_bfloat162*)xh)[2*i]   = h01;
    ((__nv_bfloat162*)xh)[2*i+1] = h23;
    ((__nv_bfloat162*)xl)[2*i]   = l01;
    ((__nv_bfloat162*)xl)[2*i+1] = l23;
}

// ---------------------------------------------------------------------------
// Fused transpose+split of all 4 weights (blockIdx.z): W[k][n] -> wh/wl[n][k]
// ---------------------------------------------------------------------------
__global__ void __launch_bounds__(256) trans_split4_kernel(
    const float* __restrict__ W0, const float* __restrict__ W1,
    const float* __restrict__ W2, const float* __restrict__ W3,
    __nv_bfloat16* __restrict__ wh, __nv_bfloat16* __restrict__ wl)
{
    __shared__ float t[32][33];
    const int z = blockIdx.z;
    const float* W = (z == 0) ? W0 : (z == 1) ? W1 : (z == 2) ? W2 : W3;
    const size_t zo = (size_t)z * DM * DM;
    const int k0 = blockIdx.y * 32, n0 = blockIdx.x * 32;
    const int tx = threadIdx.x, ty = threadIdx.y;     // (32, 8)
    #pragma unroll
    for (int j = 0; j < 4; j++)
        t[ty + j*8][tx] = W[(size_t)(k0 + ty + j*8) * DM + n0 + tx];
    __syncthreads();
    #pragma unroll
    for (int j = 0; j < 4; j++) {
        int nn = ty + j*8;
        float v = t[tx][nn];                           // = W[k0+tx][n0+nn]
        __nv_bfloat16 h = __float2bfloat16(v);
        size_t idx = zo + (size_t)(n0 + nn) * DM + k0 + tx;
        wh[idx] = h;
        wl[idx] = __float2bfloat16(v - __bfloat162float(h));
    }
}

// ---------------------------------------------------------------------------
// GEMM geometry: R10-proven (BM128/BN128/BK32, 2-stage, 2 CTAs/SM).
// Single barrier per chunk + staggered LDSM batches (R13, measured 87.5us).
// ---------------------------------------------------------------------------
#define BM 128
#define BN 128
#define BK 32
#define STR 40
#define TILE_ELEMS (BM * STR)
#define STAGE_ELEMS (4 * TILE_ELEMS)
#define GEMM_SMEM (2 * STAGE_ELEMS * 2)       // 81920 B
#define NCHUNK (DM / BK)                      // 32
#define TSTR 132                              // fp32 transpose stride (MODE 2)

// ---------------------------------------------------------------------------
// Fused Q+K projection: blockIdx.z in {0,1}; BOTH use the MODE-1 epilogue.
// ---------------------------------------------------------------------------
__global__ void __launch_bounds__(256, 2) gemm_qk_kernel(
    const __nv_bfloat16* __restrict__ Ah0, const __nv_bfloat16* __restrict__ Al0,
    const __nv_bfloat16* __restrict__ Ah1, const __nv_bfloat16* __restrict__ Al1,
    const __nv_bfloat16* __restrict__ Wh,  const __nv_bfloat16* __restrict__ Wl,
    const float* __restrict__ bq, const float* __restrict__ bk,
    __nv_bfloat16* __restrict__ qh, __nv_bfloat16* __restrict__ ql,
    __nv_bfloat16* __restrict__ kh, __nv_bfloat16* __restrict__ kl)
{
    extern __shared__ __nv_bfloat16 sm[];
    const uint32_t sbase = smem_u32(sm);

    const int tid  = threadIdx.x;
    const int lane = tid & 31;
    const int wid  = tid >> 5;
    const int wm   = (wid >> 2) * 64;
    const int wn   = (wid & 3) * 32;
    const int bm   = blockIdx.y * BM;
    const int bn   = blockIdx.x * BN;
    const int z    = blockIdx.z;

    const __nv_bfloat16* Ah = z ? Ah1 : Ah0;
    const __nv_bfloat16* Al = z ? Al1 : Al0;
    const __nv_bfloat16* Bh = Wh + (size_t)z * DM * DM;
    const __nv_bfloat16* Bl = Wl + (size_t)z * DM * DM;
    const float* bias = z ? bk : bq;
    __nv_bfloat16* Ch = z ? kh : qh;
    __nv_bfloat16* Cl = z ? kl : ql;

    float acc[4][4][4];
    #pragma unroll
    for (int i = 0; i < 4; i++)
        #pragma unroll
        for (int j = 0; j < 4; j++)
            #pragma unroll
            for (int c = 0; c < 4; c++) acc[i][j][c] = 0.f;

    const int a_r  = wm + (lane & 7) + ((lane >> 3) & 1) * 8;
    const int a_k  = (lane >> 4) * 8;
    const int b_r  = wn + (lane & 7) + (lane >> 4) * 8;
    const int b_k  = ((lane >> 3) & 1) * 8;

    auto issue_chunk = [&](int c, int stg) {
        const int k0 = c * BK;
        const uint32_t sA = sbase + (uint32_t)(stg * STAGE_ELEMS) * 2;
        #pragma unroll
        for (int i = 0; i < 2; i++) {
            int t = tid + i * 256;
            int r = t >> 2, cc = (t & 3) * 8;
            uint32_t so = (uint32_t)(r * STR + cc) * 2;
            size_t ga = (size_t)(bm + r) * DM + k0 + cc;
            size_t gb = (size_t)(bn + r) * DM + k0 + cc;
            cp16(sA + so,                      Ah + ga);
            cp16(sA + TILE_ELEMS*2 + so,       Al + ga);
            cp16(sA + 2*TILE_ELEMS*2 + so,     Bh + gb);
            cp16(sA + 3*TILE_ELEMS*2 + so,     Bl + gb);
        }
        CP_COMMIT();
    };

    issue_chunk(0, 0);

    for (int c = 0; c < NCHUNK; c++) {
        CP_WAIT(0);
        __syncthreads();                       // single barrier per chunk
        if (c + 1 < NCHUNK) issue_chunk(c + 1, (c + 1) & 1);

        const uint32_t sA  = sbase + (uint32_t)((c & 1) * STAGE_ELEMS) * 2;
        const uint32_t sAl = sA + TILE_ELEMS * 2;
        const uint32_t sB  = sA + 2 * TILE_ELEMS * 2;
        const uint32_t sBl = sA + 3 * TILE_ELEMS * 2;

        #pragma unroll
        for (int ks = 0; ks < BK / 16; ks++) {
            uint32_t ra[4][4], rbh[2][4], rbl[2][4];
            #pragma unroll
            for (int mi = 0; mi < 4; mi++)
                ldm_x4(ra[mi], sA + (uint32_t)((a_r + mi*16) * STR + ks*16 + a_k) * 2);
            #pragma unroll
            for (int n2 = 0; n2 < 2; n2++)
                ldm_x4(rbh[n2], sB + (uint32_t)((b_r + n2*16) * STR + ks*16 + b_k) * 2);
            #pragma unroll
            for (int mi = 0; mi < 4; mi++)
                #pragma unroll
                for (int ni = 0; ni < 4; ni++)
                    mma_bf16(acc[mi][ni], ra[mi], &rbh[ni >> 1][(ni & 1) * 2]);
            #pragma unroll
            for (int n2 = 0; n2 < 2; n2++)
                ldm_x4(rbl[n2], sBl + (uint32_t)((b_r + n2*16) * STR + ks*16 + b_k) * 2);
            #pragma unroll
            for (int mi = 0; mi < 4; mi++)
                #pragma unroll
                for (int ni = 0; ni < 4; ni++)
                    mma_bf16(acc[mi][ni], ra[mi], &rbl[ni >> 1][(ni & 1) * 2]);
            #pragma unroll
            for (int mi = 0; mi < 4; mi++)
                ldm_x4(ra[mi], sAl + (uint32_t)((a_r + mi*16) * STR + ks*16 + a_k) * 2);
            #pragma unroll
            for (int mi = 0; mi < 4; mi++)
                #pragma unroll
                for (int ni = 0; ni < 4; ni++)
                    mma_bf16(acc[mi][ni], ra[mi], &rbh[ni >> 1][(ni & 1) * 2]);
        }
        __syncthreads();                       // compute done before next overwrite
    }

    const int er = lane >> 2;
    const int ec = (lane & 3) * 2;
    #pragma unroll
    for (int mi = 0; mi < 4; mi++) {
        #pragma unroll
        for (int ni = 0; ni < 4; ni++) {
            const int n  = bn + wn + ni * 8 + ec;
            const float b0 = bias[n], b1 = bias[n + 1];
            #pragma unroll
            for (int half = 0; half < 2; half++) {
                const int m = bm + wm + mi * 16 + er + half * 8;
                float v0 = acc[mi][ni][half * 2 + 0] + b0;
                float v1 = acc[mi][ni][half * 2 + 1] + b1;
                float h0 = bf16_round(v0), h1 = bf16_round(v1);
                const int b_ = m >> 11;
                const int s  = m & (SEQ - 1);
                const int h  = n >> 6;
                const int d  = n & (HD - 1);
                size_t idx = ((((size_t)b_ * NH + h) * SEQ) + s) * HD + d;
                *(uint32_t*)&Ch[idx] = pack_bf16(h0, h1);
                *(uint32_t*)&Cl[idx] = pack_bf16(v0 - h0, v1 - h1);
            }
        }
    }
}

// ---------------------------------------------------------------------------
// Templated GEMM for V (MODE 2) and O (MODE 0).
// ---------------------------------------------------------------------------
template<int MODE>
__global__ void __launch_bounds__(256, 2) gemm_mma_kernel(
    const __nv_bfloat16* __restrict__ Ah, const __nv_bfloat16* __restrict__ Al,
    const __nv_bfloat16* __restrict__ Bh, const __nv_bfloat16* __restrict__ Bl,
    const float* __restrict__ bias, float* __restrict__ Cf,
    __nv_bfloat16* __restrict__ Ch, __nv_bfloat16* __restrict__ Cl)
{
    extern __shared__ __nv_bfloat16 sm[];
    const uint32_t sbase = smem_u32(sm);

    const int tid  = threadIdx.x;
    const int lane = tid & 31;
    const int wid  = tid >> 5;
    const int wm   = (wid >> 2) * 64;
    const int wn   = (wid & 3) * 32;
    const int bm   = blockIdx.y * BM;
    const int bn   = blockIdx.x * BN;

    float acc[4][4][4];
    #pragma unroll
    for (int i = 0; i < 4; i++)
        #pragma unroll
        for (int j = 0; j < 4; j++)
            #pragma unroll
            for (int c = 0; c < 4; c++) acc[i][j][c] = 0.f;

    const int a_r  = wm + (lane & 7) + ((lane >> 3) & 1) * 8;
    const int a_k  = (lane >> 4) * 8;
    const int b_r  = wn + (lane & 7) + (lane >> 4) * 8;
    const int b_k  = ((lane >> 3) & 1) * 8;

    auto issue_chunk = [&](int c, int stg) {
        const int k0 = c * BK;
        const uint32_t sA = sbase + (uint32_t)(stg * STAGE_ELEMS) * 2;
        #pragma unroll
        for (int i = 0; i < 2; i++) {
            int t = tid + i * 256;
            int r = t >> 2, cc = (t & 3) * 8;
            uint32_t so = (uint32_t)(r * STR + cc) * 2;
            size_t ga = (size_t)(bm + r) * DM + k0 + cc;
            size_t gb = (size_t)(bn + r) * DM + k0 + cc;
            cp16(sA + so,                      Ah + ga);
            cp16(sA + TILE_ELEMS*2 + so,       Al + ga);
            cp16(sA + 2*TILE_ELEMS*2 + so,     Bh + gb);
            cp16(sA + 3*TILE_ELEMS*2 + so,     Bl + gb);
        }
        CP_COMMIT();
    };

    issue_chunk(0, 0);

    for (int c = 0; c < NCHUNK; c++) {
        CP_WAIT(0);
        __syncthreads();                       // single barrier per chunk
        if (c + 1 < NCHUNK) issue_chunk(c + 1, (c + 1) & 1);

        const uint32_t sA  = sbase + (uint32_t)((c & 1) * STAGE_ELEMS) * 2;
        const uint32_t sAl = sA + TILE_ELEMS * 2;
        const uint32_t sB  = sA + 2 * TILE_ELEMS * 2;
        const uint32_t sBl = sA + 3 * TILE_ELEMS * 2;

        #pragma unroll
        for (int ks = 0; ks < BK / 16; ks++) {
            uint32_t ra[4][4], rbh[2][4], rbl[2][4];
            #pragma unroll
            for (int mi = 0; mi < 4; mi++)
                ldm_x4(ra[mi], sA + (uint32_t)((a_r + mi*16) * STR + ks*16 + a_k) * 2);
            #pragma unroll
            for (int n2 = 0; n2 < 2; n2++)
                ldm_x4(rbh[n2], sB + (uint32_t)((b_r + n2*16) * STR + ks*16 + b_k) * 2);
            #pragma unroll
            for (int mi = 0; mi < 4; mi++)
                #pragma unroll
                for (int ni = 0; ni < 4; ni++)
                    mma_bf16(acc[mi][ni], ra[mi], &rbh[ni >> 1][(ni & 1) * 2]);
            #pragma unroll
            for (int n2 = 0; n2 < 2; n2++)
                ldm_x4(rbl[n2], sBl + (uint32_t)((b_r + n2*16) * STR + ks*16 + b_k) * 2);
            #pragma unroll
            for (int mi = 0; mi < 4; mi++)
                #pragma unroll
                for (int ni = 0; ni < 4; ni++)
                    mma_bf16(acc[mi][ni], ra[mi], &rbl[ni >> 1][(ni & 1) * 2]);
            #pragma unroll
            for (int mi = 0; mi < 4; mi++)
                ldm_x4(ra[mi], sAl + (uint32_t)((a_r + mi*16) * STR + ks*16 + a_k) * 2);
            #pragma unroll
            for (int mi = 0; mi < 4; mi++)
                #pragma unroll
                for (int ni = 0; ni < 4; ni++)
                    mma_bf16(acc[mi][ni], ra[mi], &rbh[ni >> 1][(ni & 1) * 2]);
        }
        __syncthreads();                       // compute done before next overwrite
    }

    const int er = lane >> 2;
    const int ec = (lane & 3) * 2;

    if (MODE == 2) {
        // smem-transposed epilogue: coalesced writes to [B,H,Dh,S]
        float* smf = (float*)sm;           // 128 x TSTR fp32 (67584 B < 81920)
        #pragma unroll
        for (int mi = 0; mi < 4; mi++)
            #pragma unroll
            for (int ni = 0; ni < 4; ni++) {
                const int n = wn + ni * 8 + ec;
                const float b0 = bias[bn + n], b1 = bias[bn + n + 1];
                #pragma unroll
                for (int half = 0; half < 2; half++) {
                    const int m = wm + mi * 16 + er + half * 8;
                    smf[(n)     * TSTR + m] = acc[mi][ni][half * 2 + 0] + b0;
                    smf[(n + 1) * TSTR + m] = acc[mi][ni][half * 2 + 1] + b1;
                }
            }
        __syncthreads();
        const int b_ = bm >> 11;
        #pragma unroll
        for (int i = 0; i < 16; i++) {
            const int n  = wid * 16 + i;           // local col 0..127
            const int gn = bn + n;
            const int h  = gn >> 6, d = gn & 63;
            float4 v = *(const float4*)&smf[n * TSTR + lane * 4];
            float h0 = bf16_round(v.x), h1 = bf16_round(v.y);
            float h2 = bf16_round(v.z), h3 = bf16_round(v.w);
            size_t base = (((size_t)b_ * NH + h) * HD + d) * SEQ
                        + (bm & (SEQ - 1)) + lane * 4;
            *(uint32_t*)&Ch[base]     = pack_bf16(h0, h1);
            *(uint32_t*)&Ch[base + 2] = pack_bf16(h2, h3);
            *(uint32_t*)&Cl[base]     = pack_bf16(v.x - h0, v.y - h1);
            *(uint32_t*)&Cl[base + 2] = pack_bf16(v.z - h2, v.w - h3);
        }
        return;
    }

    #pragma unroll
    for (int mi = 0; mi < 4; mi++) {
        #pragma unroll
        for (int ni = 0; ni < 4; ni++) {
            const int n  = bn + wn + ni * 8 + ec;
            const float b0 = bias[n], b1 = bias[n + 1];
            #pragma unroll
            for (int half = 0; half < 2; half++) {
                const int m = bm + wm + mi * 16 + er + half * 8;
                float2 o;
                o.x = acc[mi][ni][half * 2 + 0] + b0;
                o.y = acc[mi][ni][half * 2 + 1] + b1;
                *(float2*)&Cf[(size_t)m * DM + n] = o;
            }
        }
    }
}

// ---------------------------------------------------------------------------
// Tensor-core flash attention, split bf16 (3-pass per GEMM).
// CTA: 64 queries of one (b,h); 128 thr / 4 warps; warp = 16 rows.
// K double-buffered, V single-buffered; 72KB smem; FORCED 3 CTAs/SM.
// ---------------------------------------------------------------------------
#define ASTR 72
#define ATILE (64 * ASTR)                     // 4608 bf16 elems
#define ATT_SMEM (8 * ATILE * 2)              // 73728 B

__global__ void __launch_bounds__(128, 3) attn_mma_kernel(
    const __nv_bfloat16* __restrict__ qh, const __nv_bfloat16* __restrict__ ql,
    const __nv_bfloat16* __restrict__ kh, const __nv_bfloat16* __restrict__ kl,
    const __nv_bfloat16* __restrict__ vh, const __nv_bfloat16* __restrict__ vl,
    __nv_bfloat16* __restrict__ oh, __nv_bfloat16* __restrict__ ol)
{
    extern __shared__ __nv_bfloat16 smA[];
    const uint32_t sb  = smem_u32(smA);
    const int tid  = threadIdx.x;
    const int lane = tid & 31;
    const int w    = tid >> 5;
    const int bh   = blockIdx.y;              // b*NH + h
    const int q0   = blockIdx.x * 64;
    const size_t bo = (size_t)bh * SEQ * HD;

    const uint32_t sQh = sb;
    const uint32_t sQl = sb + ATILE * 2;
    const uint32_t sVh = sb + 6 * ATILE * 2;
    const uint32_t sVl = sb + 7 * ATILE * 2;

    auto issue_K = [&](int t, int stg) {
        const int c0 = t * 64;
        const uint32_t base = sb + (uint32_t)(2 + 2 * stg) * ATILE * 2;
        const __nv_bfloat16* gkh = kh + bo + (size_t)c0 * HD;
        const __nv_bfloat16* gkl = kl + bo + (size_t)c0 * HD;
        #pragma unroll
        for (int i = 0; i < 4; i++) {
            int e = tid + i * 128;
            int r = e >> 3, c8 = (e & 7) * 8;
            uint32_t so = (uint32_t)(r * ASTR + c8) * 2;
            cp16(base + so,             gkh + r * HD + c8);
            cp16(base + ATILE*2 + so,   gkl + r * HD + c8);
        }
    };
    auto issue_V = [&](int t) {
        const int c0 = t * 64;
        const __nv_bfloat16* gvh = vh + bo + c0;
        const __nv_bfloat16* gvl = vl + bo + c0;
        #pragma unroll
        for (int i = 0; i < 4; i++) {
            int e = tid + i * 128;
            int r = e >> 3, c8 = (e & 7) * 8;
            uint32_t so = (uint32_t)(r * ASTR + c8) * 2;
            cp16(sVh + so, gvh + (size_t)r * SEQ + c8);
            cp16(sVl + so, gvl + (size_t)r * SEQ + c8);
        }
    };

    // prologue: G0 = {Q, K0}, G1 = {V0}
    {
        const __nv_bfloat16* gqh = qh + bo + (size_t)q0 * HD;
        const __nv_bfloat16* gql = ql + bo + (size_t)q0 * HD;
        #pragma unroll
        for (int i = 0; i < 4; i++) {
            int e = tid + i * 128;
            int r = e >> 3, c8 = (e & 7) * 8;
            uint32_t so = (uint32_t)(r * ASTR + c8) * 2;
            cp16(sQh + so, gqh + r * HD + c8);
            cp16(sQl + so, gql + r * HD + c8);
        }
        issue_K(0, 0);
        CP_COMMIT();
        issue_V(0);
        CP_COMMIT();
    }

    const int a_r = w * 16 + (lane & 7) + ((lane >> 3) & 1) * 8;
    const int a_k = (lane >> 4) * 8;
    const int b_r = (lane & 7) + (lane >> 4) * 8;
    const int b_k = ((lane >> 3) & 1) * 8;

    uint32_t qfh[4][4];
    float m_i[2] = {-1e30f, -1e30f}, l_i[2] = {0.f, 0.f};
    float accO[8][4];
    #pragma unroll
    for (int j = 0; j < 8; j++)
        #pragma unroll
        for (int c = 0; c < 4; c++) accO[j][c] = 0.f;

    for (int t = 0; t < SEQ / 64; t++) {
        if (t + 1 < SEQ / 64) { issue_K(t + 1, (t + 1) & 1); CP_COMMIT(); }
        if (t + 1 < SEQ / 64) { CP_WAIT(2); } else { CP_WAIT(1); }
        __syncthreads();                       // sync_K

        if (t == 0) {
            #pragma unroll
            for (int ks = 0; ks < 4; ks++)
                ldm_x4(qfh[ks], sQh + (uint32_t)(a_r * ASTR + ks*16 + a_k) * 2);
        }

        const uint32_t sK  = sb + (uint32_t)(2 + 2 * (t & 1)) * ATILE * 2;
        const uint32_t sKl = sK + ATILE * 2;

        // ---- scores: S = Qh Kh^T + Qh Kl^T + Ql Kh^T -------------------
        float accS[8][4];
        #pragma unroll
        for (int j = 0; j < 8; j++)
            #pragma unroll
            for (int c = 0; c < 4; c++) accS[j][c] = 0.f;

        #pragma unroll
        for (int ks = 0; ks < 4; ks++) {
            uint32_t qfl[4], bhf[4][4], blf[4][4];
            ldm_x4(qfl, sQl + (uint32_t)(a_r * ASTR + ks*16 + a_k) * 2);
            #pragma unroll
            for (int n2 = 0; n2 < 4; n2++) {
                ldm_x4(bhf[n2], sK  + (uint32_t)((b_r + n2*16) * ASTR + ks*16 + b_k) * 2);
                ldm_x4(blf[n2], sKl + (uint32_t)((b_r + n2*16) * ASTR + ks*16 + b_k) * 2);
            }
            #pragma unroll
            for (int j = 0; j < 8; j++)
                mma_bf16(accS[j], qfh[ks], &bhf[j >> 1][(j & 1) * 2]);
            #pragma unroll
            for (int j = 0; j < 8; j++)
                mma_bf16(accS[j], qfh[ks], &blf[j >> 1][(j & 1) * 2]);
            #pragma unroll
            for (int j = 0; j < 8; j++)
                mma_bf16(accS[j], qfl, &bhf[j >> 1][(j & 1) * 2]);
        }

        // ---- online softmax, both row-halves phase-parallel ------------
        #pragma unroll
        for (int j = 0; j < 8; j++)
            #pragma unroll
            for (int c = 0; c < 4; c++) accS[j][c] *= 0.125f;

        float mx0 = -1e30f, mx1 = -1e30f;
        #pragma unroll
        for (int j = 0; j < 8; j++) {
            mx0 = fmaxf(mx0, fmaxf(accS[j][0], accS[j][1]));
            mx1 = fmaxf(mx1, fmaxf(accS[j][2], accS[j][3]));
        }
        mx0 = fmaxf(mx0, __shfl_xor_sync(0xffffffffu, mx0, 1));
        mx1 = fmaxf(mx1, __shfl_xor_sync(0xffffffffu, mx1, 1));
        mx0 = fmaxf(mx0, __shfl_xor_sync(0xffffffffu, mx0, 2));
        mx1 = fmaxf(mx1, __shfl_xor_sync(0xffffffffu, mx1, 2));
        const float mn0 = fmaxf(m_i[0], mx0), mn1 = fmaxf(m_i[1], mx1);
        const float al0 = __expf(m_i[0] - mn0), al1 = __expf(m_i[1] - mn1);
        m_i[0] = mn0; m_i[1] = mn1;
        float s0 = 0.f, s1 = 0.f;
        #pragma unroll
        for (int j = 0; j < 8; j++) {
            float p0 = __expf(accS[j][0] - mn0);
            float p1 = __expf(accS[j][1] - mn0);
            float p2 = __expf(accS[j][2] - mn1);
            float p3 = __expf(accS[j][3] - mn1);
            accS[j][0] = p0; accS[j][1] = p1; accS[j][2] = p2; accS[j][3] = p3;
            s0 += p0 + p1; s1 += p2 + p3;
        }
        s0 += __shfl_xor_sync(0xffffffffu, s0, 1);
        s1 += __shfl_xor_sync(0xffffffffu, s1, 1);
        s0 += __shfl_xor_sync(0xffffffffu, s0, 2);
        s1 += __shfl_xor_sync(0xffffffffu, s1, 2);
        l_i[0] = l_i[0] * al0 + s0;
        l_i[1] = l_i[1] * al1 + s1;
        #pragma unroll
        for (int j = 0; j < 8; j++) {
            accO[j][0] *= al0; accO[j][1] *= al0;
            accO[j][2] *= al1; accO[j][3] *= al1;
        }

        // ---- P -> A-fragments, split bf16 ------------------------------
        uint32_t pah[4][4], pal[4][4];
        #pragma unroll
        for (int ks = 0; ks < 4; ks++) {
            const int j0 = 2*ks, j1 = j0 + 1;
            #pragma unroll
            for (int q = 0; q < 4; q++) {
                const int jj = (q < 2) ? j0 : j1;
                const int c0 = (q & 1) * 2;
                float v0 = accS[jj][c0], v1 = accS[jj][c0 + 1];
                float h0 = bf16_round(v0), h1 = bf16_round(v1);
                pah[ks][q] = pack_bf16(h0, h1);
                pal[ks][q] = pack_bf16(v0 - h0, v1 - h1);
            }
        }

        if (t + 1 < SEQ / 64) { CP_WAIT(1); } else { CP_WAIT(0); }
        __syncthreads();                       // sync_V

        // ---- O += Ph Vh + Ph Vl + Pl Vh --------------------------------
        #pragma unroll
        for (int ks = 0; ks < 4; ks++) {
            uint32_t bvh[4][4], bvl[4][4];
            #pragma unroll
            for (int n2 = 0; n2 < 4; n2++) {
                ldm_x4(bvh[n2], sVh + (uint32_t)((b_r + n2*16) * ASTR + ks*16 + b_k) * 2);
                ldm_x4(bvl[n2], sVl + (uint32_t)((b_r + n2*16) * ASTR + ks*16 + b_k) * 2);
            }
            #pragma unroll
            for (int j = 0; j < 8; j++)
                mma_bf16(accO[j], pah[ks], &bvh[j >> 1][(j & 1) * 2]);
            #pragma unroll
            for (int j = 0; j < 8; j++)
                mma_bf16(accO[j], pah[ks], &bvl[j >> 1][(j & 1) * 2]);
            #pragma unroll
            for (int j = 0; j < 8; j++)
                mma_bf16(accO[j], pal[ks], &bvh[j >> 1][(j & 1) * 2]);
        }
        __syncthreads();                       // sync_end: V reads done

        if (t + 1 < SEQ / 64) { issue_V(t + 1); CP_COMMIT(); }
    }

    // ---- epilogue: normalize, split, write [B,S,DM] bf16 hi/lo ---------
    const int b_  = bh >> 4, hh_ = bh & 15;
    const int er  = lane >> 2, ec = (lane & 3) * 2;
    #pragma unroll
    for (int hh = 0; hh < 2; hh++) {
        const float inv = 1.f / l_i[hh];
        const int m = q0 + w * 16 + er + hh * 8;
        const size_t rowbase = ((size_t)(b_ * SEQ + m)) * DM + hh_ * HD;
        #pragma unroll
        for (int j = 0; j < 8; j++) {
            float o0 = accO[j][hh*2]   * inv;
            float o1 = accO[j][hh*2+1] * inv;
            float h0 = bf16_round(o0), h1 = bf16_round(o1);
            *(uint32_t*)&oh[rowbase + j*8 + ec] = pack_bf16(h0, h1);
            *(uint32_t*)&ol[rowbase + j*8 + ec] = pack_bf16(o0 - h0, o1 - h1);
        }
    }
}

// ---------------------------------------------------------------------------
// Launch: fork-join stream overlap.
//   main: [evA] split_act3 [evC] (wait evB) gemm_qk (wait evD) attn  gemm_O
//   s2:   (wait evA) trans_split4 [evB] (wait evC) gemm_V [evD]
// Streams/events created per call (host objects; deterministic; no device
// allocation). They are intentionally not destroyed: kernel_launch runs only
// for the correctness call and the capture call, and destroying capture-
// participating streams before EndCapture is illegal.
// ---------------------------------------------------------------------------
extern "C" void kernel_launch(void* const* d_in, const int* in_sizes, int n_in,
                              void* d_out, int out_size)
{
    const float* Q  = (const float*)d_in[0];
    const float* K  = (const float*)d_in[1];
    const float* V  = (const float*)d_in[2];
    const float* Wq = (const float*)d_in[3];
    const float* bq = (const float*)d_in[4];
    const float* Wk = (const float*)d_in[5];
    const float* bk = (const float*)d_in[6];
    const float* Wv = (const float*)d_in[7];
    const float* bv = (const float*)d_in[8];
    const float* Wo = (const float*)d_in[9];
    const float* bo = (const float*)d_in[10];
    float* out = (float*)d_out;

    __nv_bfloat16 *ah, *al, *wh, *wl, *qh, *ql, *kh, *kl, *vh, *vl;
    cudaGetSymbolAddress((void**)&ah, g_ah);
    cudaGetSymbolAddress((void**)&al, g_al);
    cudaGetSymbolAddress((void**)&wh, g_wh);
    cudaGetSymbolAddress((void**)&wl, g_wl);
    cudaGetSymbolAddress((void**)&qh, g_qh);
    cudaGetSymbolAddress((void**)&ql, g_ql);
    cudaGetSymbolAddress((void**)&kh, g_kh);
    cudaGetSymbolAddress((void**)&kl, g_kl);
    cudaGetSymbolAddress((void**)&vh, g_vh);
    cudaGetSymbolAddress((void**)&vl, g_vl);

    cudaFuncSetAttribute(gemm_qk_kernel,
                         cudaFuncAttributeMaxDynamicSharedMemorySize, GEMM_SMEM);
    cudaFuncSetAttribute(gemm_mma_kernel<0>,
                         cudaFuncAttributeMaxDynamicSharedMemorySize, GEMM_SMEM);
    cudaFuncSetAttribute(gemm_mma_kernel<2>,
                         cudaFuncAttributeMaxDynamicSharedMemorySize, GEMM_SMEM);
    cudaFuncSetAttribute(attn_mma_kernel,
                         cudaFuncAttributeMaxDynamicSharedMemorySize, ATT_SMEM);

    cudaStream_t s2;
    cudaStreamCreateWithFlags(&s2, cudaStreamNonBlocking);
    cudaEvent_t evA, evB, evC, evD;
    cudaEventCreateWithFlags(&evA, cudaEventDisableTiming);
    cudaEventCreateWithFlags(&evB, cudaEventDisableTiming);
    cudaEventCreateWithFlags(&evC, cudaEventDisableTiming);
    cudaEventCreateWithFlags(&evD, cudaEventDisableTiming);

    const size_t AZ = (size_t)MTOK * DM, WZ = (size_t)DM * DM;
    const dim3 gridS(MTOK * DM / 4 / 256, 3);
    const dim3 gridT(DM / 32, DM / 32, 4), blkT(32, 8);
    const dim3 gridQK(DM / BN, MTOK / BM, 2);   // (8, 32, 2)
    const dim3 gridG(DM / BN, MTOK / BM);       // (8, 32)
    const dim3 gridA(SEQ / 64, BATCH * NH);

    // fork s2 off the main (capture) stream
    cudaEventRecord(evA, 0);
    cudaStreamWaitEvent(s2, evA, 0);

    // s2: weight transpose+split, then V GEMM (after activations split)
    trans_split4_kernel<<<gridT, blkT, 0, s2>>>(Wq, Wk, Wv, Wo, wh, wl);
    cudaEventRecord(evB, s2);

    // main: activation split
    split_act3_kernel<<<gridS, 256>>>(Q, K, V, ah, al);
    cudaEventRecord(evC, 0);

    // s2: V projection (needs split acts + weights; both ordered on s2)
    cudaStreamWaitEvent(s2, evC, 0);
    gemm_mma_kernel<2><<<gridG, 256, GEMM_SMEM, s2>>>(ah + 2*AZ, al + 2*AZ,
                                                      wh + 2*WZ, wl + 2*WZ, bv,
                                                      nullptr, vh, vl);
    cudaEventRecord(evD, s2);

    // main: fused Q+K projections (needs weights from s2)
    cudaStreamWaitEvent(0, evB, 0);
    gemm_qk_kernel<<<gridQK, 256, GEMM_SMEM>>>(ah, al, ah + AZ, al + AZ,
                                               wh, wl, bq, bk,
                                               qh, ql, kh, kl);

    // join: attention needs q,k (main) and v (s2)
    cudaStreamWaitEvent(0, evD, 0);
    attn_mma_kernel<<<gridA, 128, ATT_SMEM>>>(qh, ql, kh, kl, vh, vl, ah, al);

    // output projection -> fp32 d_out
    gemm_mma_kernel<0><<<gridG, 256, GEMM_SMEM>>>(ah, al,
                                                  wh + 3*WZ, wl + 3*WZ, bo,
                                                  out, nullptr, nullptr);
}